// round 15
// baseline (speedup 1.0000x reference)
#include <cuda_runtime.h>
#include <cuda_fp16.h>
#include <cstdint>
#include <math.h>

#define BATCH   4096
#define IN_DIM  1024
#define OUT_DIM 1024
#define NK      96
#define RANK    192
#define SCALE_F 0.03125f                    // 1/32 exactly
#define G_SCALE 1024.0f
#define SCALE_EPI (SCALE_F / G_SCALE)

typedef __half h16;

// ---------------- scratch (device globals) ----------------------------------
__device__ h16 g_Fhi[RANK * IN_DIM];     // [192][1024] K-major
__device__ h16 g_Ghi[OUT_DIM * RANK];    // [1024][192] K-major, scaled by 1024
__device__ h16 g_Th [BATCH * RANK];

// ---------------- helpers ----------------------------------------------------
__device__ __forceinline__ uint32_t smem_u32(const void* p) {
    uint32_t a;
    asm("{ .reg .u64 t; cvta.to.shared.u64 t, %1; cvt.u32.u64 %0, t; }" : "=r"(a) : "l"(p));
    return a;
}
__device__ __forceinline__ void cp_async16(uint32_t s, const void* g) {
    asm volatile("cp.async.cg.shared.global [%0], [%1], 16;\n" :: "r"(s), "l"(g));
}
__device__ __forceinline__ void cp_commit() {
    asm volatile("cp.async.commit_group;\n" ::: "memory");
}
template <int N>
__device__ __forceinline__ void cp_wait() {
    asm volatile("cp.async.wait_group %0;\n" :: "n"(N) : "memory");
}
__device__ __forceinline__ void ldm_x4(uint32_t& r0, uint32_t& r1, uint32_t& r2, uint32_t& r3,
                                       uint32_t addr) {
    asm volatile("ldmatrix.sync.aligned.m8n8.x4.shared.b16 {%0,%1,%2,%3}, [%4];"
                 : "=r"(r0), "=r"(r1), "=r"(r2), "=r"(r3) : "r"(addr));
}
__device__ __forceinline__ void mma_fp16(float* c, const uint32_t* a, uint32_t b0, uint32_t b1) {
    asm volatile(
        "mma.sync.aligned.m16n8k16.row.col.f32.f16.f16.f32 "
        "{%0,%1,%2,%3}, {%4,%5,%6,%7}, {%8,%9}, {%0,%1,%2,%3};"
        : "+f"(c[0]), "+f"(c[1]), "+f"(c[2]), "+f"(c[3])
        : "r"(a[0]), "r"(a[1]), "r"(a[2]), "r"(a[3]), "r"(b0), "r"(b1));
}
__device__ __forceinline__ void sts128(uint32_t addr, uint32_t a, uint32_t b, uint32_t c,
                                       uint32_t d) {
    asm volatile("st.shared.v4.b32 [%0], {%1,%2,%3,%4};" :: "r"(addr), "r"(a), "r"(b),
                 "r"(c), "r"(d) : "memory");
}
__device__ __forceinline__ uint32_t h2u(__half2 h) { return *reinterpret_cast<uint32_t*>(&h); }

// ---------------------------------------------------------------------------
// prep: factor build only.
//   blocks [0,192)  F factor (fast sincos, coalesced half2 stores)
//   blocks [192,384) G factor (fast sincos, scaled, coalesced half2 stores)
// ---------------------------------------------------------------------------
__global__ void prep_kernel(const float* __restrict__ omega,
                            const float* __restrict__ phi,
                            const float* __restrict__ alpha) {
    int b = blockIdx.x;
    if (b < 192) {
        int idx = b * 256 + threadIdx.x;
        int i2 = (idx & 511) << 1;
        int k  = idx >> 9;
        float w0 = omega[3 * k + 0];
        float s0, c0, s1, c1;
        __sincosf(w0 * ((float)(i2 + 1) / 1025.0f), &s0, &c0);
        __sincosf(w0 * ((float)(i2 + 2) / 1025.0f), &s1, &c1);
        __half2* Fhi2 = reinterpret_cast<__half2*>(g_Fhi);
        Fhi2[(k * 1024 + i2) >> 1]        = __floats2half2_rn(s0, s1);
        Fhi2[((NK + k) * 1024 + i2) >> 1] = __floats2half2_rn(c0, c1);
        return;
    }
    int idx = (b - 192) * 256 + threadIdx.x;
    int kp = idx % 48;
    int j  = idx / 48;
    int k2 = kp << 1;
    float p = (float)(j + 1) / 1025.0f;

    float gs[2], gc[2];
#pragma unroll
    for (int q = 0; q < 2; q++) {
        int k = k2 + q;
        float w1 = omega[3 * k + 1], w2 = omega[3 * k + 2];
        float Bv = fmaf(w1, p, fmaf(w2, 0.5f, phi[k]));
        float sb, cb;
        __sincosf(Bv, &sb, &cb);
        float as = alpha[k], ac = alpha[NK + k];
        gs[q] = (as * cb - ac * sb) * G_SCALE;
        gc[q] = (as * sb + ac * cb) * G_SCALE;
    }
    __half2* Ghi2 = reinterpret_cast<__half2*>(g_Ghi);
    Ghi2[(j * RANK + k2) >> 1]      = __floats2half2_rn(gs[0], gs[1]);
    Ghi2[(j * RANK + NK + k2) >> 1] = __floats2half2_rn(gc[0], gc[1]);
}

// ---------------------------------------------------------------------------
// GEMM1 (fused x convert): Th = fp16( x @ F^T ).
// A: fp32 x loaded via LDG into register ping-pong, cvt->STS fp16 into smem.
// B: F fp16 via cp.async. ldmatrix for both fragments. BM=64, BN=64, BK=64,
// 256 thr (4x2 warps, warp tile 16x32), 3-stage ring, 16 iterations.
// ---------------------------------------------------------------------------
__global__ __launch_bounds__(256, 2) void gemm1_kernel(
    const float* __restrict__ X,
    const h16* __restrict__ B,
    h16* __restrict__ Ch) {
    constexpr int KA = IN_DIM;
    constexpr int STR = 72;                  // 64 + 8 pad (halves)
    constexpr int SS = (64 + 64) * STR;      // halves per stage (9216)
    constexpr int STAGES = 3, NC = 16;

    extern __shared__ h16 smem[];
    const uint32_t su = smem_u32(smem);

    const int t = threadIdx.x, w = t >> 5, lane = t & 31;
    const int wm = w & 3, wn = w >> 2;       // 4 warps M (16 rows), 2 warps N (32 cols)
    const int m0 = blockIdx.y * 64, n0 = blockIdx.x * 64;

    const int r4 = t >> 2;                   // 0..63 (A row)
    const int cq = t & 3;                    // 16-float column group

    // ---- A path: LDG fp32 -> regs -> cvt -> STS fp16 ----
    float4 rA0[4], rA1[4];
    auto ldgA = [&](int c, float4* rg) {
        if (c < NC) {
            const float4* src = reinterpret_cast<const float4*>(
                X + (size_t)(m0 + r4) * KA + c * 64 + cq * 16);
#pragma unroll
            for (int q = 0; q < 4; q++) rg[q] = src[q];
        }
    };
    auto stsA = [&](int c, const float4* rg) {
        if (c < NC) {
            uint32_t h[8];
#pragma unroll
            for (int q = 0; q < 4; q++) {
                h[2 * q]     = h2u(__floats2half2_rn(rg[q].x, rg[q].y));
                h[2 * q + 1] = h2u(__floats2half2_rn(rg[q].z, rg[q].w));
            }
            uint32_t addr = su + ((c % STAGES) * SS + r4 * STR + cq * 16) * 2;
            sts128(addr,      h[0], h[1], h[2], h[3]);
            sts128(addr + 16, h[4], h[5], h[6], h[7]);
        }
    };

    // ---- B path: cp.async fp16 ----
    auto issueB = [&](int c) {
        const uint32_t sbase = su + (c % STAGES) * SS * 2;
        int r = t >> 3, c8 = (t & 7) * 8;
#pragma unroll
        for (int i = 0; i < 2; i++) {
            int rr = r + i * 32;
            cp_async16(sbase + ((64 + rr) * STR + c8) * 2,
                       B + (size_t)(n0 + rr) * KA + c * 64 + c8);
        }
        cp_commit();
    };

    float acc[4][4];
#pragma unroll
    for (int ni = 0; ni < 4; ni++)
#pragma unroll
        for (int q = 0; q < 4; q++) acc[ni][q] = 0.0f;

    auto compute = [&](int buf) {
        const uint32_t sbase = su + buf * SS * 2;
        uint32_t aF[4][4], bF[4][2][4];
#pragma unroll
        for (int kk = 0; kk < 4; kk++) {
            uint32_t addr = sbase +
                ((wm * 16 + (lane & 15)) * STR + kk * 16 + (lane >> 4) * 8) * 2;
            ldm_x4(aF[kk][0], aF[kk][1], aF[kk][2], aF[kk][3], addr);
        }
#pragma unroll
        for (int kk = 0; kk < 4; kk++)
#pragma unroll
            for (int nj = 0; nj < 2; nj++) {
                uint32_t addr = sbase + (64 * STR) * 2 +
                    ((wn * 32 + nj * 16 + (lane & 15)) * STR + kk * 16 + (lane >> 4) * 8) * 2;
                ldm_x4(bF[kk][nj][0], bF[kk][nj][1], bF[kk][nj][2], bF[kk][nj][3], addr);
            }
#pragma unroll
        for (int kk = 0; kk < 4; kk++)
#pragma unroll
            for (int nj = 0; nj < 2; nj++) {
                mma_fp16(acc[2 * nj],     aF[kk], bF[kk][nj][0], bF[kk][nj][2]);
                mma_fp16(acc[2 * nj + 1], aF[kk], bF[kk][nj][1], bF[kk][nj][3]);
            }
    };

    // prologue
    ldgA(0, rA0);
    ldgA(1, rA1);
    stsA(0, rA0);
    issueB(0);
    issueB(1);

#pragma unroll 1
    for (int c = 0; c < NC; c += 2) {
        // even iteration c
        ldgA(c + 2, rA0);                 // overwrite A(c), already STS'd
        cp_wait<1>();
        __syncthreads();                   // publishes A(c) STS + B(c)
        stsA(c + 1, rA1);
        if (c + 2 < NC) issueB(c + 2); else cp_commit();
        compute(c % STAGES);
        // odd iteration c+1
        ldgA(c + 3, rA1);
        cp_wait<1>();
        __syncthreads();
        stsA(c + 2, rA0);
        if (c + 3 < NC) issueB(c + 3); else cp_commit();
        compute((c + 1) % STAGES);
    }

    {
        int r0 = m0 + wm * 16 + (lane >> 2);
#pragma unroll
        for (int ni = 0; ni < 4; ni++) {
            int cc = n0 + wn * 32 + ni * 8 + (lane & 3) * 2;
            *reinterpret_cast<__half2*>(Ch + (size_t)r0 * RANK + cc) =
                __floats2half2_rn(acc[ni][0], acc[ni][1]);
            *reinterpret_cast<__half2*>(Ch + (size_t)(r0 + 8) * RANK + cc) =
                __floats2half2_rn(acc[ni][2], acc[ni][3]);
        }
    }
}

// ---------------------------------------------------------------------------
// GEMM2: out = SCALE_EPI*(Th @ G'^T) + bias. fp16 single pass, BK=32.
// BM=128, BN=64, 256 thr (4x2 warps), 4-stage ring, 6 iterations.
// ---------------------------------------------------------------------------
__global__ __launch_bounds__(256, 3) void gemm2_kernel(
    const h16* __restrict__ A,
    const h16* __restrict__ B,
    float* __restrict__ Cf, const float* __restrict__ bias) {
    constexpr int KA = RANK;
    constexpr int STR = 40;                  // 32 + 8 pad
    constexpr int SS = (128 + 64) * STR;     // halves per stage
    constexpr int STAGES = 4, NC = 6;

    extern __shared__ h16 smem[];
    const uint32_t su = smem_u32(smem);

    const int t = threadIdx.x, w = t >> 5, lane = t & 31;
    const int wm = w & 3, wn = w >> 2;
    const int m0 = blockIdx.y * 128, n0 = blockIdx.x * 64;

    auto issue = [&](int c, int buf) {
        const int k0 = c * 32;
        const uint32_t sbase = su + buf * SS * 2;
#pragma unroll
        for (int i = 0; i < 3; i++) {
            int idx = t + i * 256;
            int r = idx >> 2, c8 = (idx & 3) * 8;
            const h16* g;
            uint32_t soff;
            if (r < 128) { g = A + (size_t)(m0 + r) * KA + k0 + c8;                soff = r * STR + c8; }
            else         { int rr = r - 128; g = B + (size_t)(n0 + rr) * KA + k0 + c8; soff = (128 + rr) * STR + c8; }
            cp_async16(sbase + soff * 2, g);
        }
        cp_commit();
    };

    float acc[2][4][4];
#pragma unroll
    for (int mi = 0; mi < 2; mi++)
#pragma unroll
        for (int ni = 0; ni < 4; ni++)
#pragma unroll
            for (int q = 0; q < 4; q++) acc[mi][ni][q] = 0.0f;

    auto compute = [&](int buf) {
        const uint32_t sbase = su + buf * SS * 2;
        uint32_t aF[2][2][4], bF[2][2][4];
#pragma unroll
        for (int kk = 0; kk < 2; kk++)
#pragma unroll
            for (int mi = 0; mi < 2; mi++) {
                uint32_t addr = sbase +
                    ((wm * 32 + mi * 16 + (lane & 15)) * STR + kk * 16 + (lane >> 4) * 8) * 2;
                ldm_x4(aF[kk][mi][0], aF[kk][mi][1], aF[kk][mi][2], aF[kk][mi][3], addr);
            }
#pragma unroll
        for (int kk = 0; kk < 2; kk++)
#pragma unroll
            for (int nj = 0; nj < 2; nj++) {
                uint32_t addr = sbase + (128 * STR) * 2 +
                    ((wn * 32 + nj * 16 + (lane & 15)) * STR + kk * 16 + (lane >> 4) * 8) * 2;
                ldm_x4(bF[kk][nj][0], bF[kk][nj][1], bF[kk][nj][2], bF[kk][nj][3], addr);
            }
#pragma unroll
        for (int kk = 0; kk < 2; kk++)
#pragma unroll
            for (int mi = 0; mi < 2; mi++)
#pragma unroll
                for (int nj = 0; nj < 2; nj++) {
                    mma_fp16(acc[mi][2 * nj],     aF[kk][mi], bF[kk][nj][0], bF[kk][nj][2]);
                    mma_fp16(acc[mi][2 * nj + 1], aF[kk][mi], bF[kk][nj][1], bF[kk][nj][3]);
                }
    };

#pragma unroll 1
    for (int s = 0; s < STAGES - 1; s++) issue(s, s);
#pragma unroll 1
    for (int c = 0; c < NC; c++) {
        cp_wait<STAGES - 2>();
        __syncthreads();
        if (c + STAGES - 1 < NC) issue(c + STAGES - 1, (c + STAGES - 1) % STAGES);
        else cp_commit();
        compute(c % STAGES);
    }

#pragma unroll
    for (int mi = 0; mi < 2; mi++) {
        int r0 = m0 + wm * 32 + mi * 16 + (lane >> 2);
#pragma unroll
        for (int ni = 0; ni < 4; ni++) {
            int cc = n0 + wn * 32 + ni * 8 + (lane & 3) * 2;
            float b0 = bias[cc], b1 = bias[cc + 1];
            float2 o0 = {acc[mi][ni][0] * SCALE_EPI + b0, acc[mi][ni][1] * SCALE_EPI + b1};
            float2 o1 = {acc[mi][ni][2] * SCALE_EPI + b0, acc[mi][ni][3] * SCALE_EPI + b1};
            *reinterpret_cast<float2*>(Cf + (size_t)r0 * OUT_DIM + cc) = o0;
            *reinterpret_cast<float2*>(Cf + (size_t)(r0 + 8) * OUT_DIM + cc) = o1;
        }
    }
}

// ---------------------------------------------------------------------------
extern "C" void kernel_launch(void* const* d_in, const int* in_sizes, int n_in,
                              void* d_out, int out_size) {
    const float* x     = (const float*)d_in[0];
    const float* omega = (const float*)d_in[1];
    const float* phi   = (const float*)d_in[2];
    const float* alpha = (const float*)d_in[3];
    const float* bias  = (const float*)d_in[4];
    float* out = (float*)d_out;

    h16 *Fhi, *Ghi, *Th;
    cudaGetSymbolAddress((void**)&Fhi, g_Fhi);
    cudaGetSymbolAddress((void**)&Ghi, g_Ghi);
    cudaGetSymbolAddress((void**)&Th,  g_Th);

    const int SMEM1 = 3 * (64 + 64) * 72 * 2;   // 55296
    const int SMEM2 = 4 * (128 + 64) * 40 * 2;  // 61440
    cudaFuncSetAttribute((const void*)gemm1_kernel,
                         cudaFuncAttributeMaxDynamicSharedMemorySize, SMEM1);
    cudaFuncSetAttribute((const void*)gemm2_kernel,
                         cudaFuncAttributeMaxDynamicSharedMemorySize, SMEM2);

    // prep: factor build only (F: [0,192), G: [192,384))
    prep_kernel<<<384, 256>>>(omega, phi, alpha);

    // GEMM1: Th = fp16(x @ F^T)   (M=4096, N=192, K=1024), grid 3 x 64 = 192 CTAs
    gemm1_kernel<<<dim3(RANK / 64, BATCH / 64), 256, SMEM1>>>(x, Fhi, Th);

    // GEMM2: out = SCALE_EPI*(Th @ G'^T) + bias  (M=4096, N=1024, K=192), grid 16 x 32 = 512
    gemm2_kernel<<<dim3(OUT_DIM / 64, BATCH / 128), 256, SMEM2>>>(Th, Ghi, out, bias);
}

// round 16
// speedup vs baseline: 1.1957x; 1.1957x over previous
#include <cuda_runtime.h>
#include <cuda_fp16.h>
#include <cstdint>
#include <math.h>

#define BATCH   4096
#define IN_DIM  1024
#define OUT_DIM 1024
#define NK      96
#define RANK    192
#define SCALE_F 0.03125f                    // 1/32 exactly
#define G_SCALE 1024.0f
#define SCALE_EPI (SCALE_F / G_SCALE)

typedef __half h16;

// ---------------- scratch (device globals) ----------------------------------
__device__ h16 g_xh [BATCH * IN_DIM];
__device__ h16 g_Fhi[RANK * IN_DIM];     // [192][1024] K-major
__device__ h16 g_Ghi[OUT_DIM * RANK];    // [1024][192] K-major, scaled by 1024
__device__ h16 g_Th [BATCH * RANK];

// ---------------- helpers ----------------------------------------------------
__device__ __forceinline__ uint32_t smem_u32(const void* p) {
    uint32_t a;
    asm("{ .reg .u64 t; cvta.to.shared.u64 t, %1; cvt.u32.u64 %0, t; }" : "=r"(a) : "l"(p));
    return a;
}
__device__ __forceinline__ void cp_async16(uint32_t s, const void* g) {
    asm volatile("cp.async.cg.shared.global [%0], [%1], 16;\n" :: "r"(s), "l"(g));
}
__device__ __forceinline__ void cp_commit() {
    asm volatile("cp.async.commit_group;\n" ::: "memory");
}
template <int N>
__device__ __forceinline__ void cp_wait() {
    asm volatile("cp.async.wait_group %0;\n" :: "n"(N) : "memory");
}
__device__ __forceinline__ void ldm_x4(uint32_t& r0, uint32_t& r1, uint32_t& r2, uint32_t& r3,
                                       uint32_t addr) {
    asm volatile("ldmatrix.sync.aligned.m8n8.x4.shared.b16 {%0,%1,%2,%3}, [%4];"
                 : "=r"(r0), "=r"(r1), "=r"(r2), "=r"(r3) : "r"(addr));
}
__device__ __forceinline__ void mma_fp16(float* c, const uint32_t* a, uint32_t b0, uint32_t b1) {
    asm volatile(
        "mma.sync.aligned.m16n8k16.row.col.f32.f16.f16.f32 "
        "{%0,%1,%2,%3}, {%4,%5,%6,%7}, {%8,%9}, {%0,%1,%2,%3};"
        : "+f"(c[0]), "+f"(c[1]), "+f"(c[2]), "+f"(c[3])
        : "r"(a[0]), "r"(a[1]), "r"(a[2]), "r"(a[3]), "r"(b0), "r"(b1));
}
__device__ __forceinline__ uint32_t h2u(__half2 h) { return *reinterpret_cast<uint32_t*>(&h); }

// ---------------------------------------------------------------------------
// prep: blocks [0,512) x->fp16 (MLP=8, 16B stores)
//       blocks [512,704) F factor (fast sincos, coalesced half2 stores)
//       blocks [704,896) G factor (fast sincos, scaled, coalesced half2 stores)
// ---------------------------------------------------------------------------
__global__ void prep_kernel(const float4* __restrict__ x,
                            const float* __restrict__ omega,
                            const float* __restrict__ phi,
                            const float* __restrict__ alpha) {
    int b = blockIdx.x;
    if (b < 512) {
        int tid = b * 256 + threadIdx.x;
        uint4* dst = reinterpret_cast<uint4*>(g_xh);
        float4 v[8];
#pragma unroll
        for (int p = 0; p < 4; p++) {
            int base = 2 * (tid + p * 131072);
            v[2 * p]     = x[base];
            v[2 * p + 1] = x[base + 1];
        }
#pragma unroll
        for (int p = 0; p < 4; p++) {
            float4 a = v[2 * p], c = v[2 * p + 1];
            uint4 o;
            o.x = h2u(__floats2half2_rn(a.x, a.y));
            o.y = h2u(__floats2half2_rn(a.z, a.w));
            o.z = h2u(__floats2half2_rn(c.x, c.y));
            o.w = h2u(__floats2half2_rn(c.z, c.w));
            dst[tid + p * 131072] = o;
        }
        return;
    }
    if (b < 704) {
        int idx = (b - 512) * 256 + threadIdx.x;
        int i2 = (idx & 511) << 1;
        int k  = idx >> 9;
        float w0 = omega[3 * k + 0];
        float s0, c0, s1, c1;
        __sincosf(w0 * ((float)(i2 + 1) / 1025.0f), &s0, &c0);
        __sincosf(w0 * ((float)(i2 + 2) / 1025.0f), &s1, &c1);
        __half2* Fhi2 = reinterpret_cast<__half2*>(g_Fhi);
        Fhi2[(k * 1024 + i2) >> 1]        = __floats2half2_rn(s0, s1);
        Fhi2[((NK + k) * 1024 + i2) >> 1] = __floats2half2_rn(c0, c1);
        return;
    }
    int idx = (b - 704) * 256 + threadIdx.x;
    int kp = idx % 48;
    int j  = idx / 48;
    int k2 = kp << 1;
    float p = (float)(j + 1) / 1025.0f;

    float gs[2], gc[2];
#pragma unroll
    for (int q = 0; q < 2; q++) {
        int k = k2 + q;
        float w1 = omega[3 * k + 1], w2 = omega[3 * k + 2];
        float Bv = fmaf(w1, p, fmaf(w2, 0.5f, phi[k]));
        float sb, cb;
        __sincosf(Bv, &sb, &cb);
        float as = alpha[k], ac = alpha[NK + k];
        gs[q] = (as * cb - ac * sb) * G_SCALE;
        gc[q] = (as * sb + ac * cb) * G_SCALE;
    }
    __half2* Ghi2 = reinterpret_cast<__half2*>(g_Ghi);
    Ghi2[(j * RANK + k2) >> 1]      = __floats2half2_rn(gs[0], gs[1]);
    Ghi2[(j * RANK + NK + k2) >> 1] = __floats2half2_rn(gc[0], gc[1]);
}

// ---------------------------------------------------------------------------
// GEMM1: Th = fp16(x @ F^T). fp16 single pass, BK=64 per pipeline iteration.
// BM=64, BN=64, 256 thr (4x2 warps, warp tile 16x32), 3-stage ring, 16 iters.
// (R13 configuration — best measured.)
// ---------------------------------------------------------------------------
__global__ __launch_bounds__(256, 2) void gemm1_kernel(
    const h16* __restrict__ A,
    const h16* __restrict__ B,
    h16* __restrict__ Ch) {
    constexpr int KA = IN_DIM;
    constexpr int STR = 72;                  // 64 + 8 pad (halves)
    constexpr int SS = (64 + 64) * STR;      // halves per stage (9216)
    constexpr int STAGES = 3, NC = 16;

    extern __shared__ h16 smem[];
    const uint32_t su = smem_u32(smem);

    const int t = threadIdx.x, w = t >> 5, lane = t & 31;
    const int wm = w & 3, wn = w >> 2;       // 4 warps M (16 rows), 2 warps N (32 cols)
    const int m0 = blockIdx.y * 64, n0 = blockIdx.x * 64;

    auto issue = [&](int c, int buf) {
        const int k0 = c * 64;
        const uint32_t sbase = su + buf * SS * 2;
        int r = t >> 3, c8 = (t & 7) * 8;
#pragma unroll
        for (int i = 0; i < 2; i++) {
            int rr = r + i * 32;
            cp_async16(sbase + (rr * STR + c8) * 2, A + (size_t)(m0 + rr) * KA + k0 + c8);
        }
#pragma unroll
        for (int i = 0; i < 2; i++) {
            int rr = r + i * 32;
            cp_async16(sbase + ((64 + rr) * STR + c8) * 2, B + (size_t)(n0 + rr) * KA + k0 + c8);
        }
        cp_commit();
    };

    float acc[4][4];
#pragma unroll
    for (int ni = 0; ni < 4; ni++)
#pragma unroll
        for (int q = 0; q < 4; q++) acc[ni][q] = 0.0f;

    auto compute = [&](int buf) {
        const uint32_t sbase = su + buf * SS * 2;
        uint32_t aF[4][4], bF[4][2][4];
#pragma unroll
        for (int kk = 0; kk < 4; kk++) {
            uint32_t addr = sbase +
                ((wm * 16 + (lane & 15)) * STR + kk * 16 + (lane >> 4) * 8) * 2;
            ldm_x4(aF[kk][0], aF[kk][1], aF[kk][2], aF[kk][3], addr);
        }
#pragma unroll
        for (int kk = 0; kk < 4; kk++)
#pragma unroll
            for (int nj = 0; nj < 2; nj++) {
                uint32_t addr = sbase + (64 * STR) * 2 +
                    ((wn * 32 + nj * 16 + (lane & 15)) * STR + kk * 16 + (lane >> 4) * 8) * 2;
                ldm_x4(bF[kk][nj][0], bF[kk][nj][1], bF[kk][nj][2], bF[kk][nj][3], addr);
            }
#pragma unroll
        for (int kk = 0; kk < 4; kk++)
#pragma unroll
            for (int nj = 0; nj < 2; nj++) {
                mma_fp16(acc[2 * nj],     aF[kk], bF[kk][nj][0], bF[kk][nj][2]);
                mma_fp16(acc[2 * nj + 1], aF[kk], bF[kk][nj][1], bF[kk][nj][3]);
            }
    };

#pragma unroll 1
    for (int s = 0; s < STAGES - 1; s++) issue(s, s);
#pragma unroll 1
    for (int c = 0; c < NC; c++) {
        cp_wait<STAGES - 2>();
        __syncthreads();
        if (c + STAGES - 1 < NC) issue(c + STAGES - 1, (c + STAGES - 1) % STAGES);
        else cp_commit();
        compute(c % STAGES);
    }

    {
        int r0 = m0 + wm * 16 + (lane >> 2);
#pragma unroll
        for (int ni = 0; ni < 4; ni++) {
            int cc = n0 + wn * 32 + ni * 8 + (lane & 3) * 2;
            *reinterpret_cast<__half2*>(Ch + (size_t)r0 * RANK + cc) =
                __floats2half2_rn(acc[ni][0], acc[ni][1]);
            *reinterpret_cast<__half2*>(Ch + (size_t)(r0 + 8) * RANK + cc) =
                __floats2half2_rn(acc[ni][2], acc[ni][3]);
        }
    }
}

// ---------------------------------------------------------------------------
// GEMM2: out = SCALE_EPI*(Th @ G'^T) + bias. fp16 single pass, BK=32.
// BM=128, BN=128, 512 thr (4x4 warps, warp tile 32x32), 4-stage ring, 6 iters.
// grid = 8 x 32 = 256 CTAs @ 2 CTA/SM -> SINGLE WAVE (capacity 296).
// ---------------------------------------------------------------------------
__global__ __launch_bounds__(512, 2) void gemm2_kernel(
    const h16* __restrict__ A,
    const h16* __restrict__ B,
    float* __restrict__ Cf, const float* __restrict__ bias) {
    constexpr int KA = RANK;
    constexpr int STR = 40;                  // 32 + 8 pad
    constexpr int SS = (128 + 128) * STR;    // halves per stage (10240)
    constexpr int STAGES = 4, NC = 6;

    extern __shared__ h16 smem[];
    const uint32_t su = smem_u32(smem);

    const int t = threadIdx.x, w = t >> 5, lane = t & 31;
    const int wm = w & 3, wn = w >> 2;       // 4 warps M (32 rows), 4 warps N (32 cols)
    const int m0 = blockIdx.y * 128, n0 = blockIdx.x * 128;

    auto issue = [&](int c, int buf) {
        const int k0 = c * 32;
        const uint32_t sbase = su + buf * SS * 2;
#pragma unroll
        for (int i = 0; i < 2; i++) {
            int idx = t + i * 512;
            int r = idx >> 2, c8 = (idx & 3) * 8;
            const h16* g;
            uint32_t soff;
            if (r < 128) { g = A + (size_t)(m0 + r) * KA + k0 + c8;                soff = r * STR + c8; }
            else         { int rr = r - 128; g = B + (size_t)(n0 + rr) * KA + k0 + c8; soff = (128 + rr) * STR + c8; }
            cp_async16(sbase + soff * 2, g);
        }
        cp_commit();
    };

    float acc[2][4][4];
#pragma unroll
    for (int mi = 0; mi < 2; mi++)
#pragma unroll
        for (int ni = 0; ni < 4; ni++)
#pragma unroll
            for (int q = 0; q < 4; q++) acc[mi][ni][q] = 0.0f;

    auto compute = [&](int buf) {
        const uint32_t sbase = su + buf * SS * 2;
        uint32_t aF[2][2][4], bF[2][2][4];
#pragma unroll
        for (int kk = 0; kk < 2; kk++)
#pragma unroll
            for (int mi = 0; mi < 2; mi++) {
                uint32_t addr = sbase +
                    ((wm * 32 + mi * 16 + (lane & 15)) * STR + kk * 16 + (lane >> 4) * 8) * 2;
                ldm_x4(aF[kk][mi][0], aF[kk][mi][1], aF[kk][mi][2], aF[kk][mi][3], addr);
            }
#pragma unroll
        for (int kk = 0; kk < 2; kk++)
#pragma unroll
            for (int nj = 0; nj < 2; nj++) {
                uint32_t addr = sbase + (128 * STR) * 2 +
                    ((wn * 32 + nj * 16 + (lane & 15)) * STR + kk * 16 + (lane >> 4) * 8) * 2;
                ldm_x4(bF[kk][nj][0], bF[kk][nj][1], bF[kk][nj][2], bF[kk][nj][3], addr);
            }
#pragma unroll
        for (int kk = 0; kk < 2; kk++)
#pragma unroll
            for (int mi = 0; mi < 2; mi++)
#pragma unroll
                for (int nj = 0; nj < 2; nj++) {
                    mma_fp16(acc[mi][2 * nj],     aF[kk][mi], bF[kk][nj][0], bF[kk][nj][2]);
                    mma_fp16(acc[mi][2 * nj + 1], aF[kk][mi], bF[kk][nj][1], bF[kk][nj][3]);
                }
    };

#pragma unroll 1
    for (int s = 0; s < STAGES - 1; s++) issue(s, s);
#pragma unroll 1
    for (int c = 0; c < NC; c++) {
        cp_wait<STAGES - 2>();
        __syncthreads();
        if (c + STAGES - 1 < NC) issue(c + STAGES - 1, (c + STAGES - 1) % STAGES);
        else cp_commit();
        compute(c % STAGES);
    }

#pragma unroll
    for (int mi = 0; mi < 2; mi++) {
        int r0 = m0 + wm * 32 + mi * 16 + (lane >> 2);
#pragma unroll
        for (int ni = 0; ni < 4; ni++) {
            int cc = n0 + wn * 32 + ni * 8 + (lane & 3) * 2;
            float b0 = bias[cc], b1 = bias[cc + 1];
            float2 o0 = {acc[mi][ni][0] * SCALE_EPI + b0, acc[mi][ni][1] * SCALE_EPI + b1};
            float2 o1 = {acc[mi][ni][2] * SCALE_EPI + b0, acc[mi][ni][3] * SCALE_EPI + b1};
            *reinterpret_cast<float2*>(Cf + (size_t)r0 * OUT_DIM + cc) = o0;
            *reinterpret_cast<float2*>(Cf + (size_t)(r0 + 8) * OUT_DIM + cc) = o1;
        }
    }
}

// ---------------------------------------------------------------------------
extern "C" void kernel_launch(void* const* d_in, const int* in_sizes, int n_in,
                              void* d_out, int out_size) {
    const float* x     = (const float*)d_in[0];
    const float* omega = (const float*)d_in[1];
    const float* phi   = (const float*)d_in[2];
    const float* alpha = (const float*)d_in[3];
    const float* bias  = (const float*)d_in[4];
    float* out = (float*)d_out;

    h16 *xh, *Fhi, *Ghi, *Th;
    cudaGetSymbolAddress((void**)&xh,  g_xh);
    cudaGetSymbolAddress((void**)&Fhi, g_Fhi);
    cudaGetSymbolAddress((void**)&Ghi, g_Ghi);
    cudaGetSymbolAddress((void**)&Th,  g_Th);

    const int SMEM1 = 3 * (64 + 64) * 72 * 2;    // 55296, 2 CTA/SM
    const int SMEM2 = 4 * (128 + 128) * 40 * 2;  // 81920, 2 CTA/SM
    cudaFuncSetAttribute((const void*)gemm1_kernel,
                         cudaFuncAttributeMaxDynamicSharedMemorySize, SMEM1);
    cudaFuncSetAttribute((const void*)gemm2_kernel,
                         cudaFuncAttributeMaxDynamicSharedMemorySize, SMEM2);

    // prep: [0,512) convert x, [512,704) F, [704,896) G
    prep_kernel<<<896, 256>>>((const float4*)x, omega, phi, alpha);

    // GEMM1: Th = fp16(x @ F^T)   (M=4096, N=192, K=1024), grid 3 x 64 = 192 CTAs
    gemm1_kernel<<<dim3(RANK / 64, BATCH / 64), 256, SMEM1>>>(xh, Fhi, Th);

    // GEMM2: out = SCALE_EPI*(Th @ G'^T) + bias  (M=4096, N=1024, K=192), grid 8 x 32 = 256
    gemm2_kernel<<<dim3(OUT_DIM / 128, BATCH / 128), 512, SMEM2>>>(Th, Ghi, out, bias);
}